// round 2
// baseline (speedup 1.0000x reference)
#include <cuda_runtime.h>
#include <mma.h>
#include <cstdint>

using namespace nvcuda;

#define D_MODEL   1024
#define D_STATE   128
#define D_INNER   2048
#define NHEADS    32
#define HEADDIM   64
#define CONV_DIM  2304
#define D_IN_PROJ 4384
#define SEQLEN    2048
#define BATCH     2
#define BL        (BATCH * SEQLEN)   // 4096

// ---------------- device scratch (no allocations allowed) ----------------
__device__ float g_zx[(size_t)BL * D_IN_PROJ];    // in_proj output  [4096, 4384]
__device__ float g_xconv[(size_t)BL * CONV_DIM];  // conv+silu out   [4096, 2304]
__device__ float g_dtp[(size_t)BL * NHEADS];      // softplus(dt+bias)
__device__ float g_dA[(size_t)BL * NHEADS];       // exp(dt*A)
__device__ float g_y[(size_t)BL * D_INNER];       // scan output + D*x
__device__ float g_nrm[(size_t)BL * D_INNER];     // gated + rmsnormed

// =====================================================================
// GEMM: C[M,N] = A[M,K] (row-major) * B[N,K]^T (row-major), optional +resid
// tf32 WMMA with 3-term split (AhBh + AlBh + AhBl) for ~fp32 accuracy.
// =====================================================================
#define BMT 128
#define BNT 128
#define BKT 32
#define LDT (BKT + 4)

__global__ __launch_bounds__(256) void gemm_tf32_split(
    const float* __restrict__ A, const float* __restrict__ B,
    float* __restrict__ C, const float* __restrict__ resid,
    int M, int N, int K)
{
    __shared__ float As[BMT][LDT];
    __shared__ float Bs[BNT][LDT];
    const int bm  = blockIdx.y * BMT;
    const int bn  = blockIdx.x * BNT;
    const int tid = threadIdx.x;
    const int wid = tid >> 5;
    const int wm  = (wid & 3) * 32;   // 4 warps along M (32 rows each)
    const int wn  = (wid >> 2) * 64;  // 2 warps along N (64 cols each)

    wmma::fragment<wmma::accumulator, 16, 16, 8, float> acc[2][4];
#pragma unroll
    for (int i = 0; i < 2; i++)
#pragma unroll
        for (int j = 0; j < 4; j++) wmma::fill_fragment(acc[i][j], 0.0f);

    for (int k0 = 0; k0 < K; k0 += BKT) {
        // load A tile 128x32 (always in-bounds: M % 128 == 0, K % 32 == 0)
#pragma unroll
        for (int i = 0; i < 4; i++) {
            int f4 = tid + i * 256;
            int r  = f4 >> 3;
            int c  = (f4 & 7) << 2;
            float4 v = *(const float4*)(A + (size_t)(bm + r) * K + k0 + c);
            *(float4*)&As[r][c] = v;
        }
        // load B tile 128x32 with N-guard (zero fill)
#pragma unroll
        for (int i = 0; i < 4; i++) {
            int f4 = tid + i * 256;
            int r  = f4 >> 3;
            int c  = (f4 & 7) << 2;
            float4 v = make_float4(0.f, 0.f, 0.f, 0.f);
            if (bn + r < N) v = *(const float4*)(B + (size_t)(bn + r) * K + k0 + c);
            *(float4*)&Bs[r][c] = v;
        }
        __syncthreads();

#pragma unroll
        for (int kk = 0; kk < BKT; kk += 8) {
            wmma::fragment<wmma::matrix_a, 16, 16, 8, wmma::precision::tf32, wmma::row_major> ah[2], al[2];
            wmma::fragment<wmma::matrix_b, 16, 16, 8, wmma::precision::tf32, wmma::col_major> bh[4], bl[4];
#pragma unroll
            for (int i = 0; i < 2; i++) {
                wmma::load_matrix_sync(ah[i], &As[wm + i * 16][kk], LDT);
#pragma unroll
                for (int e = 0; e < ah[i].num_elements; e++) {
                    float f = ah[i].x[e];
                    float h = wmma::__float_to_tf32(f);
                    al[i].x[e] = wmma::__float_to_tf32(f - h);
                    ah[i].x[e] = h;
                }
            }
#pragma unroll
            for (int j = 0; j < 4; j++) {
                wmma::load_matrix_sync(bh[j], &Bs[wn + j * 16][kk], LDT);
#pragma unroll
                for (int e = 0; e < bh[j].num_elements; e++) {
                    float f = bh[j].x[e];
                    float h = wmma::__float_to_tf32(f);
                    bl[j].x[e] = wmma::__float_to_tf32(f - h);
                    bh[j].x[e] = h;
                }
            }
#pragma unroll
            for (int i = 0; i < 2; i++)
#pragma unroll
                for (int j = 0; j < 4; j++) {
                    wmma::mma_sync(acc[i][j], ah[i], bh[j], acc[i][j]);
                    wmma::mma_sync(acc[i][j], al[i], bh[j], acc[i][j]);
                    wmma::mma_sync(acc[i][j], ah[i], bl[j], acc[i][j]);
                }
        }
        __syncthreads();
    }

#pragma unroll
    for (int i = 0; i < 2; i++)
#pragma unroll
        for (int j = 0; j < 4; j++) {
            int row = bm + wm + i * 16;
            int col = bn + wn + j * 16;
            if (col < N) {
                if (resid != nullptr) {
                    wmma::fragment<wmma::accumulator, 16, 16, 8, float> r;
                    wmma::load_matrix_sync(r, resid + (size_t)row * N + col, N, wmma::mem_row_major);
#pragma unroll
                    for (int e = 0; e < r.num_elements; e++) acc[i][j].x[e] += r.x[e];
                }
                wmma::store_matrix_sync(C + (size_t)row * N + col, acc[i][j], N, wmma::mem_row_major);
            }
        }
}

// =====================================================================
// Causal depthwise conv (width 4) + bias + SiLU over zx cols [2048,4352)
// =====================================================================
__global__ __launch_bounds__(256) void conv_silu_kernel(
    const float* __restrict__ cw, const float* __restrict__ cb)
{
    int c   = blockIdx.x * 256 + threadIdx.x;   // 0..2303
    int row = blockIdx.y;                       // 0..4095
    int t   = row & (SEQLEN - 1);
    float4 w = *(const float4*)(cw + c * 4);
    const float* wv = (const float*)&w;
    const float* col = g_zx + (size_t)row * D_IN_PROJ + D_INNER + c;
    float s = 0.f;
#pragma unroll
    for (int j = 0; j < 4; j++) {
        int tt = t - 3 + j;
        if (tt >= 0) s = fmaf(wv[j], col[(j - 3) * D_IN_PROJ], s);
    }
    s += cb[c];
    g_xconv[(size_t)row * CONV_DIM + c] = s / (1.f + expf(-s));
}

// =====================================================================
// dt preprocessing: dtp = softplus(dt + bias), dA = exp(-exp(A_log)*dtp)
// =====================================================================
__global__ __launch_bounds__(256) void dt_kernel(
    const float* __restrict__ dt_bias, const float* __restrict__ A_log)
{
    int idx = blockIdx.x * 256 + threadIdx.x;   // BL*32
    int row = idx >> 5;
    int hh  = idx & 31;
    float v  = g_zx[(size_t)row * D_IN_PROJ + (D_INNER + CONV_DIM) + hh] + dt_bias[hh];
    float sp = (v > 20.f) ? v : log1pf(expf(v));
    g_dtp[idx] = sp;
    g_dA[idx]  = expf(-expf(A_log[hh]) * sp);
}

// =====================================================================
// Sequential selective scan: one block per (batch, head).
// 256 threads; thread (p = tid>>2, q = tid&3) owns 16 f32x2 state pairs
// (n = 2*(q*16+jp) .. +1). B/C staged through a 3-deep smem ring with
// distance-2 prefetch, pair-rotated to avoid 4-way bank conflicts.
// =====================================================================
typedef unsigned long long ull;

__device__ __forceinline__ ull f32x2_fma(ull a, ull b, ull c) {
    ull d;
    asm("fma.rn.f32x2 %0, %1, %2, %3;" : "=l"(d) : "l"(a), "l"(b), "l"(c));
    return d;
}
__device__ __forceinline__ ull f32x2_mul(ull a, ull b) {
    ull d;
    asm("mul.rn.f32x2 %0, %1, %2;" : "=l"(d) : "l"(a), "l"(b));
    return d;
}
__device__ __forceinline__ ull f32x2_pack(float x) {
    ull d;
    asm("mov.b64 %0, {%1, %2};" : "=l"(d) : "f"(x), "f"(x));
    return d;
}
__device__ __forceinline__ float f32x2_sum(ull a) {
    float lo, hi;
    asm("mov.b64 {%0, %1}, %2;" : "=f"(lo), "=f"(hi) : "l"(a));
    return lo + hi;
}

__global__ __launch_bounds__(256) void scan_kernel(const float* __restrict__ Dv)
{
    const int bi  = blockIdx.x >> 5;
    const int h   = blockIdx.x & 31;
    const int tid = threadIdx.x;
    const int p   = tid >> 2;
    const int q   = tid & 3;

    __shared__ float  s_xs[3][64];
    __shared__ float2 s_B[3][64];
    __shared__ float2 s_C[3][64];
    __shared__ float  s_sc[3][2];

    ull S[16];
#pragma unroll
    for (int i = 0; i < 16; i++) S[i] = 0ULL;

    const float Dh = Dv[h];
    const float* xcb = g_xconv + (size_t)bi * SEQLEN * CONV_DIM;
    const float* dAb = g_dA  + (size_t)bi * SEQLEN * NHEADS + h;
    const float* dtb = g_dtp + (size_t)bi * SEQLEN * NHEADS + h;

    auto stage = [&](int t, int buf) {
        const float* rowp = xcb + (size_t)t * CONV_DIM;
        if (tid < 32) {
            ((float2*)s_xs[buf])[tid] = ((const float2*)(rowp + h * 64))[tid];
        } else if (tid < 96) {
            int i = tid - 32;
            int dst = (i & 48) | ((i + ((i >> 4) << 2)) & 15);
            s_B[buf][dst] = ((const float2*)(rowp + D_INNER))[i];
        } else if (tid < 160) {
            int i = tid - 96;
            int dst = (i & 48) | ((i + ((i >> 4) << 2)) & 15);
            s_C[buf][dst] = ((const float2*)(rowp + D_INNER + D_STATE))[i];
        } else if (tid == 160) {
            s_sc[buf][0] = dAb[(size_t)t * NHEADS];
        } else if (tid == 161) {
            s_sc[buf][1] = dtb[(size_t)t * NHEADS];
        }
    };

    stage(0, 0);
    stage(1, 1);
    __syncthreads();

    int ofs[16];
#pragma unroll
    for (int jp = 0; jp < 16; jp++) ofs[jp] = (q << 4) | ((jp + (q << 2)) & 15);

    int buf = 0;
    for (int t = 0; t < SEQLEN; t++) {
        if (t + 2 < SEQLEN) {
            int nb = buf + 2; if (nb >= 3) nb -= 3;
            stage(t + 2, nb);
        }
        const float dAv = s_sc[buf][0];
        const float dtv = s_sc[buf][1];
        const float xsv = s_xs[buf][p];
        const ull dA2  = f32x2_pack(dAv);
        const ull xdt2 = f32x2_pack(xsv * dtv);
        const ull* Bb = (const ull*)s_B[buf];
        const ull* Cb = (const ull*)s_C[buf];
        ull y0 = 0ULL, y1 = 0ULL;
#pragma unroll
        for (int jp = 0; jp < 16; jp++) {
            ull bb = Bb[ofs[jp]];
            ull cc = Cb[ofs[jp]];
            ull s  = f32x2_fma(dA2, S[jp], f32x2_mul(xdt2, bb));
            S[jp] = s;
            if (jp & 1) y1 = f32x2_fma(s, cc, y1);
            else        y0 = f32x2_fma(s, cc, y0);
        }
        float yacc = f32x2_sum(y0) + f32x2_sum(y1);
        yacc += __shfl_xor_sync(0xffffffffu, yacc, 1);
        yacc += __shfl_xor_sync(0xffffffffu, yacc, 2);
        if (q == 0) {
            g_y[((size_t)bi * SEQLEN + t) * D_INNER + h * 64 + p] = fmaf(Dh, xsv, yacc);
        }
        buf = (buf == 2) ? 0 : buf + 1;
        __syncthreads();
    }
}

// =====================================================================
// y * silu(z), then RMSNorm with norm_w. One block per row.
// =====================================================================
__global__ __launch_bounds__(256) void gatenorm_kernel(const float* __restrict__ nw)
{
    int row = blockIdx.x;
    int tid = threadIdx.x;
    const float* yr = g_y  + (size_t)row * D_INNER;
    const float* zr = g_zx + (size_t)row * D_IN_PROJ;  // z = cols [0,2048)
    float v[8];
    float ss = 0.f;
#pragma unroll
    for (int i = 0; i < 8; i++) {
        int c = tid + i * 256;
        float z = zr[c];
        float val = yr[c] * (z / (1.f + expf(-z)));
        v[i] = val;
        ss = fmaf(val, val, ss);
    }
#pragma unroll
    for (int o = 16; o; o >>= 1) ss += __shfl_xor_sync(0xffffffffu, ss, o);
    __shared__ float red[8];
    if ((tid & 31) == 0) red[tid >> 5] = ss;
    __syncthreads();
    float tot = red[0] + red[1] + red[2] + red[3] + red[4] + red[5] + red[6] + red[7];
    float scale = rsqrtf(tot * (1.0f / 2048.0f) + 1e-5f);
#pragma unroll
    for (int i = 0; i < 8; i++) {
        int c = tid + i * 256;
        g_nrm[(size_t)row * D_INNER + c] = v[i] * scale * nw[c];
    }
}

// =====================================================================
extern "C" void kernel_launch(void* const* d_in, const int* in_sizes, int n_in,
                              void* d_out, int out_size)
{
    const float* x          = (const float*)d_in[0];
    const float* in_proj_w  = (const float*)d_in[1];
    const float* conv_w     = (const float*)d_in[2];
    const float* conv_b     = (const float*)d_in[3];
    const float* dt_bias    = (const float*)d_in[4];
    const float* A_log      = (const float*)d_in[5];
    const float* Dv         = (const float*)d_in[6];
    const float* norm_w     = (const float*)d_in[7];
    const float* out_proj_w = (const float*)d_in[8];
    float* out = (float*)d_out;

    float* zx  = nullptr;
    float* nrm = nullptr;
    cudaGetSymbolAddress((void**)&zx, g_zx);
    cudaGetSymbolAddress((void**)&nrm, g_nrm);

    // 1) in_proj: zx[4096,4384] = x @ in_proj_w^T
    gemm_tf32_split<<<dim3((D_IN_PROJ + BNT - 1) / BNT, BL / BMT), 256>>>(
        x, in_proj_w, zx, nullptr, BL, D_IN_PROJ, D_MODEL);

    // 2) causal conv + silu over xBC columns
    conv_silu_kernel<<<dim3(CONV_DIM / 256, BL), 256>>>(conv_w, conv_b);

    // 3) dt / dA preprocessing
    dt_kernel<<<(BL * NHEADS) / 256, 256>>>(dt_bias, A_log);

    // 4) sequential selective scan (+ D * x skip)
    scan_kernel<<<BATCH * NHEADS, 256>>>(Dv);

    // 5) gate with silu(z) + RMSNorm
    gatenorm_kernel<<<BL, 256>>>(norm_w);

    // 6) out_proj + residual: out = x + nrm @ out_proj_w^T
    gemm_tf32_split<<<dim3(D_MODEL / BNT, BL / BMT), 256>>>(
        nrm, out_proj_w, out, x, BL, D_MODEL, D_INNER);
}

// round 4
// speedup vs baseline: 1.5433x; 1.5433x over previous
#include <cuda_runtime.h>
#include <cuda_bf16.h>
#include <cstdint>

typedef unsigned long long ull;

#define D_MODEL   1024
#define D_STATE   128
#define D_INNER   2048
#define NHEADS    32
#define HEADDIM   64
#define CONV_DIM  2304
#define D_IN_PROJ 4384
#define SEQLEN    2048
#define BATCH     2
#define BL        (BATCH * SEQLEN)   // 4096

// ---------------- device scratch ----------------
__device__ float g_zx[(size_t)BL * D_IN_PROJ];
__device__ float g_xconv[(size_t)BL * CONV_DIM];
__device__ float g_dtp[(size_t)BL * NHEADS];
__device__ float g_dA[(size_t)BL * NHEADS];
__device__ float g_y[(size_t)BL * D_INNER];
__device__ __nv_bfloat16 g_xhb[(size_t)BL * D_MODEL];
__device__ __nv_bfloat16 g_xlb[(size_t)BL * D_MODEL];
__device__ __nv_bfloat16 g_w1h[(size_t)D_IN_PROJ * D_MODEL];
__device__ __nv_bfloat16 g_w1l[(size_t)D_IN_PROJ * D_MODEL];
__device__ __nv_bfloat16 g_w2h[(size_t)D_MODEL * D_INNER];
__device__ __nv_bfloat16 g_w2l[(size_t)D_MODEL * D_INNER];
__device__ __nv_bfloat16 g_nh[(size_t)BL * D_INNER];
__device__ __nv_bfloat16 g_nl[(size_t)BL * D_INNER];

// ---------------- PTX helpers ----------------
__device__ __forceinline__ uint32_t smem_u32(const void* p) {
    return (uint32_t)__cvta_generic_to_shared(p);
}
__device__ __forceinline__ void cp_async16(uint32_t dst, const void* src, int nbytes) {
    asm volatile("cp.async.cg.shared.global [%0], [%1], 16, %2;" :: "r"(dst), "l"(src), "r"(nbytes) : "memory");
}
__device__ __forceinline__ void cp_commit() { asm volatile("cp.async.commit_group;" ::: "memory"); }
template<int N> __device__ __forceinline__ void cp_wait() { asm volatile("cp.async.wait_group %0;" :: "n"(N) : "memory"); }

__device__ __forceinline__ void ldsm4(uint32_t* r, uint32_t addr) {
    asm volatile("ldmatrix.sync.aligned.m8n8.x4.shared.b16 {%0,%1,%2,%3}, [%4];"
        : "=r"(r[0]), "=r"(r[1]), "=r"(r[2]), "=r"(r[3]) : "r"(addr));
}
__device__ __forceinline__ void mma16816(float* d, const uint32_t* a, const uint32_t* b) {
    asm volatile("mma.sync.aligned.m16n8k16.row.col.f32.bf16.bf16.f32 "
        "{%0,%1,%2,%3}, {%4,%5,%6,%7}, {%8,%9}, {%0,%1,%2,%3};"
        : "+f"(d[0]), "+f"(d[1]), "+f"(d[2]), "+f"(d[3])
        : "r"(a[0]), "r"(a[1]), "r"(a[2]), "r"(a[3]), "r"(b[0]), "r"(b[1]));
}

// =====================================================================
// bf16 3-term-split GEMM: C[M,N] = (Ah+Al)[M,K] * (Bh+Bl)[N,K]^T (+resid)
// BM=128 BN=128 BK=32. 8 warps (4x2), warp tile 32x64.
// Smem rows padded to 80B (conflict-free ldmatrix). 2-stage cp.async.
// =====================================================================
#define ROW_B   80
#define TILE_B  (128 * ROW_B)       // 10240
#define STAGE_B (4 * TILE_B)        // 40960
#define GSMEM   (2 * STAGE_B)       // 81920

__global__ __launch_bounds__(256, 1) void gemm_mma(
    const __nv_bfloat16* __restrict__ Ah, const __nv_bfloat16* __restrict__ Al,
    const __nv_bfloat16* __restrict__ Bh, const __nv_bfloat16* __restrict__ Bl,
    float* __restrict__ C, const float* __restrict__ resid,
    int M, int N, int K)
{
    extern __shared__ char sm[];
    const uint32_t smb = smem_u32(sm);
    const int tid  = threadIdx.x;
    const int wid  = tid >> 5;
    const int lane = tid & 31;
    const int bm = blockIdx.y * 128;
    const int bn = blockIdx.x * 128;
    const int wm = (wid & 3) * 32;      // warp row offset (4 warps on M)
    const int wn = (wid >> 2) * 64;     // warp col offset (2 warps on N)

    const __nv_bfloat16* srcs[4] = {Ah, Al, Bh, Bl};

    auto stage = [&](int it, int buf) {
        const int k0 = it * 32;
#pragma unroll
        for (int i = 0; i < 8; i++) {
            int f = tid + i * 256;            // 0..2047
            int tsel = f >> 9;                // 0..3 (Ah,Al,Bh,Bl)
            int c = f & 511;
            int r = c >> 2;                   // 0..127
            int cc = c & 3;                   // 16B chunk
            uint32_t dst = smb + buf * STAGE_B + tsel * TILE_B + r * ROW_B + cc * 16;
            int row = (tsel < 2) ? (bm + r) : (bn + r);
            int nb = 16;
            if (tsel >= 2 && row >= N) { row = bn; nb = 0; }
            cp_async16(dst, srcs[tsel] + (size_t)row * K + k0 + cc * 8, nb);
        }
    };

    // ldmatrix lane address components
    const int jj = lane >> 3;
    const int lr = lane & 7;
    const int aRow = (jj & 1) * 8 + lr;       // + wm + mt*16
    const int aColB = (jj >> 1) * 16;         // + ks*32
    const int bRow = (jj >> 1) * 8 + lr;      // + wn + pn*16
    const int bColB = (jj & 1) * 16;          // + ks*32

    float acc[2][8][4];
#pragma unroll
    for (int mt = 0; mt < 2; mt++)
#pragma unroll
        for (int j = 0; j < 8; j++)
#pragma unroll
            for (int e = 0; e < 4; e++) acc[mt][j][e] = 0.f;

    const int NIT = K >> 5;
    stage(0, 0);
    cp_commit();

    for (int it = 0; it < NIT; it++) {
        const int buf = it & 1;
        if (it + 1 < NIT) { stage(it + 1, buf ^ 1); cp_commit(); cp_wait<1>(); }
        else              { cp_wait<0>(); }
        __syncthreads();

        const uint32_t ab  = smb + buf * STAGE_B;
        const uint32_t alb = ab + TILE_B;
        const uint32_t bhb = ab + 2 * TILE_B;
        const uint32_t blb = ab + 3 * TILE_B;

#pragma unroll
        for (int ks = 0; ks < 2; ks++) {
            uint32_t ah[2][4], alf[2][4], bh[4][4], blf[4][4];
#pragma unroll
            for (int mt = 0; mt < 2; mt++) {
                uint32_t off = (uint32_t)((wm + mt * 16 + aRow) * ROW_B + ks * 32 + aColB);
                ldsm4(ah[mt],  ab  + off);
                ldsm4(alf[mt], alb + off);
            }
#pragma unroll
            for (int pn = 0; pn < 4; pn++) {
                uint32_t off = (uint32_t)((wn + pn * 16 + bRow) * ROW_B + ks * 32 + bColB);
                ldsm4(bh[pn],  bhb + off);
                ldsm4(blf[pn], blb + off);
            }
#pragma unroll
            for (int mt = 0; mt < 2; mt++)
#pragma unroll
                for (int j = 0; j < 8; j++) {
                    const uint32_t* bf = bh[j >> 1] + (j & 1) * 2;
                    const uint32_t* bl2 = blf[j >> 1] + (j & 1) * 2;
                    mma16816(acc[mt][j], ah[mt],  bf);
                    mma16816(acc[mt][j], alf[mt], bf);
                    mma16816(acc[mt][j], ah[mt],  bl2);
                }
        }
        __syncthreads();
    }

    // epilogue
    const int r0 = bm + wm + (lane >> 2);
#pragma unroll
    for (int mt = 0; mt < 2; mt++) {
#pragma unroll
        for (int j = 0; j < 8; j++) {
            int col = bn + wn + (j >> 1) * 16 + (j & 1) * 8 + (lane & 3) * 2;
            if (col < N) {
                int r1 = r0 + mt * 16;
                int r2 = r1 + 8;
                float2 v1 = make_float2(acc[mt][j][0], acc[mt][j][1]);
                float2 v2 = make_float2(acc[mt][j][2], acc[mt][j][3]);
                if (resid) {
                    float2 q1 = *(const float2*)(resid + (size_t)r1 * N + col);
                    float2 q2 = *(const float2*)(resid + (size_t)r2 * N + col);
                    v1.x += q1.x; v1.y += q1.y; v2.x += q2.x; v2.y += q2.y;
                }
                *(float2*)(C + (size_t)r1 * N + col) = v1;
                *(float2*)(C + (size_t)r2 * N + col) = v2;
            }
        }
    }
}

// =====================================================================
// fp32 -> bf16 hi/lo split
// =====================================================================
__global__ __launch_bounds__(256) void split_kernel(
    const float* __restrict__ src, __nv_bfloat16* __restrict__ hi,
    __nv_bfloat16* __restrict__ lo, int n)
{
    int i = blockIdx.x * 256 + threadIdx.x;
    if (i < n) {
        float v = src[i];
        __nv_bfloat16 h = __float2bfloat16_rn(v);
        hi[i] = h;
        lo[i] = __float2bfloat16_rn(v - __bfloat162float(h));
    }
}

// =====================================================================
// conv + silu
// =====================================================================
__global__ __launch_bounds__(256) void conv_silu_kernel(
    const float* __restrict__ cw, const float* __restrict__ cb)
{
    int c = blockIdx.x * 256 + threadIdx.x;
    int row = blockIdx.y;
    int t = row & (SEQLEN - 1);
    float4 w = *(const float4*)(cw + c * 4);
    const float* wv = (const float*)&w;
    const float* col = g_zx + (size_t)row * D_IN_PROJ + D_INNER + c;
    float s = 0.f;
#pragma unroll
    for (int j = 0; j < 4; j++) {
        int tt = t - 3 + j;
        if (tt >= 0) s = fmaf(wv[j], col[(j - 3) * D_IN_PROJ], s);
    }
    s += cb[c];
    g_xconv[(size_t)row * CONV_DIM + c] = s / (1.f + expf(-s));
}

__global__ __launch_bounds__(256) void dt_kernel(
    const float* __restrict__ dt_bias, const float* __restrict__ A_log)
{
    int idx = blockIdx.x * 256 + threadIdx.x;
    int row = idx >> 5;
    int hh = idx & 31;
    float v = g_zx[(size_t)row * D_IN_PROJ + (D_INNER + CONV_DIM) + hh] + dt_bias[hh];
    float sp = (v > 20.f) ? v : log1pf(expf(v));
    g_dtp[idx] = sp;
    g_dA[idx] = expf(-expf(A_log[hh]) * sp);
}

// =====================================================================
// selective scan (same structure as R1 passing kernel)
// =====================================================================
__device__ __forceinline__ ull f2fma(ull a, ull b, ull c) { ull d; asm("fma.rn.f32x2 %0, %1, %2, %3;" : "=l"(d) : "l"(a), "l"(b), "l"(c)); return d; }
__device__ __forceinline__ ull f2mul(ull a, ull b) { ull d; asm("mul.rn.f32x2 %0, %1, %2;" : "=l"(d) : "l"(a), "l"(b)); return d; }
__device__ __forceinline__ ull f2pack(float x) { ull d; asm("mov.b64 %0, {%1, %2};" : "=l"(d) : "f"(x), "f"(x)); return d; }
__device__ __forceinline__ float f2sum(ull a) { float lo, hi; asm("mov.b64 {%0, %1}, %2;" : "=f"(lo), "=f"(hi) : "l"(a)); return lo + hi; }

__global__ __launch_bounds__(256) void scan_kernel(const float* __restrict__ Dv)
{
    const int bi = blockIdx.x >> 5;
    const int h = blockIdx.x & 31;
    const int tid = threadIdx.x;
    const int p = tid >> 2;
    const int q = tid & 3;

    __shared__ float  s_xs[3][64];
    __shared__ float2 s_B[3][64];
    __shared__ float2 s_C[3][64];
    __shared__ float  s_sc[3][2];

    ull S[16];
#pragma unroll
    for (int i = 0; i < 16; i++) S[i] = 0ULL;

    const float Dh = Dv[h];
    const float* xcb = g_xconv + (size_t)bi * SEQLEN * CONV_DIM;
    const float* dAb = g_dA + (size_t)bi * SEQLEN * NHEADS + h;
    const float* dtb = g_dtp + (size_t)bi * SEQLEN * NHEADS + h;

    auto stage = [&](int t, int buf) {
        const float* rowp = xcb + (size_t)t * CONV_DIM;
        if (tid < 32) {
            ((float2*)s_xs[buf])[tid] = ((const float2*)(rowp + h * 64))[tid];
        } else if (tid < 96) {
            int i = tid - 32;
            int dst = (i & 48) | ((i + ((i >> 4) << 2)) & 15);
            s_B[buf][dst] = ((const float2*)(rowp + D_INNER))[i];
        } else if (tid < 160) {
            int i = tid - 96;
            int dst = (i & 48) | ((i + ((i >> 4) << 2)) & 15);
            s_C[buf][dst] = ((const float2*)(rowp + D_INNER + D_STATE))[i];
        } else if (tid == 160) {
            s_sc[buf][0] = dAb[(size_t)t * NHEADS];
        } else if (tid == 161) {
            s_sc[buf][1] = dtb[(size_t)t * NHEADS];
        }
    };

    stage(0, 0);
    stage(1, 1);
    __syncthreads();

    int ofs[16];
#pragma unroll
    for (int jp = 0; jp < 16; jp++) ofs[jp] = (q << 4) | ((jp + (q << 2)) & 15);

    int buf = 0;
    for (int t = 0; t < SEQLEN; t++) {
        if (t + 2 < SEQLEN) {
            int nb = buf + 2; if (nb >= 3) nb -= 3;
            stage(t + 2, nb);
        }
        const float dAv = s_sc[buf][0];
        const float dtv = s_sc[buf][1];
        const float xsv = s_xs[buf][p];
        const ull dA2 = f2pack(dAv);
        const ull xdt2 = f2pack(xsv * dtv);
        const ull* Bb = (const ull*)s_B[buf];
        const ull* Cb = (const ull*)s_C[buf];
        ull y0 = 0ULL, y1 = 0ULL;
#pragma unroll
        for (int jp = 0; jp < 16; jp++) {
            ull bb = Bb[ofs[jp]];
            ull cc = Cb[ofs[jp]];
            ull s = f2fma(dA2, S[jp], f2mul(xdt2, bb));
            S[jp] = s;
            if (jp & 1) y1 = f2fma(s, cc, y1);
            else        y0 = f2fma(s, cc, y0);
        }
        float yacc = f2sum(y0) + f2sum(y1);
        yacc += __shfl_xor_sync(0xffffffffu, yacc, 1);
        yacc += __shfl_xor_sync(0xffffffffu, yacc, 2);
        if (q == 0) {
            g_y[((size_t)bi * SEQLEN + t) * D_INNER + h * 64 + p] = fmaf(Dh, xsv, yacc);
        }
        buf = (buf == 2) ? 0 : buf + 1;
        __syncthreads();
    }
}

// =====================================================================
// gate + RMSNorm, emits bf16 hi/lo split directly
// =====================================================================
__global__ __launch_bounds__(256) void gatenorm_kernel(const float* __restrict__ nw)
{
    int row = blockIdx.x;
    int tid = threadIdx.x;
    const float* yr = g_y + (size_t)row * D_INNER;
    const float* zr = g_zx + (size_t)row * D_IN_PROJ;
    float v[8];
    float ss = 0.f;
#pragma unroll
    for (int i = 0; i < 8; i++) {
        int c = tid + i * 256;
        float z = zr[c];
        float val = yr[c] * (z / (1.f + expf(-z)));
        v[i] = val;
        ss = fmaf(val, val, ss);
    }
#pragma unroll
    for (int o = 16; o; o >>= 1) ss += __shfl_xor_sync(0xffffffffu, ss, o);
    __shared__ float red[8];
    if ((tid & 31) == 0) red[tid >> 5] = ss;
    __syncthreads();
    float tot = red[0] + red[1] + red[2] + red[3] + red[4] + red[5] + red[6] + red[7];
    float scale = rsqrtf(tot * (1.0f / 2048.0f) + 1e-5f);
#pragma unroll
    for (int i = 0; i < 8; i++) {
        int c = tid + i * 256;
        float val = v[i] * scale * nw[c];
        __nv_bfloat16 h = __float2bfloat16_rn(val);
        g_nh[(size_t)row * D_INNER + c] = h;
        g_nl[(size_t)row * D_INNER + c] = __float2bfloat16_rn(val - __bfloat162float(h));
    }
}

// =====================================================================
extern "C" void kernel_launch(void* const* d_in, const int* in_sizes, int n_in,
                              void* d_out, int out_size)
{
    const float* x          = (const float*)d_in[0];
    const float* in_proj_w  = (const float*)d_in[1];
    const float* conv_w     = (const float*)d_in[2];
    const float* conv_b     = (const float*)d_in[3];
    const float* dt_bias    = (const float*)d_in[4];
    const float* A_log      = (const float*)d_in[5];
    const float* Dv         = (const float*)d_in[6];
    const float* norm_w     = (const float*)d_in[7];
    const float* out_proj_w = (const float*)d_in[8];
    float* out = (float*)d_out;

    float *zx;
    __nv_bfloat16 *xh, *xl, *w1h, *w1l, *w2h, *w2l, *nh, *nl;
    cudaGetSymbolAddress((void**)&zx, g_zx);
    cudaGetSymbolAddress((void**)&xh, g_xhb);
    cudaGetSymbolAddress((void**)&xl, g_xlb);
    cudaGetSymbolAddress((void**)&w1h, g_w1h);
    cudaGetSymbolAddress((void**)&w1l, g_w1l);
    cudaGetSymbolAddress((void**)&w2h, g_w2h);
    cudaGetSymbolAddress((void**)&w2l, g_w2l);
    cudaGetSymbolAddress((void**)&nh, g_nh);
    cudaGetSymbolAddress((void**)&nl, g_nl);

    cudaFuncSetAttribute(gemm_mma, cudaFuncAttributeMaxDynamicSharedMemorySize, GSMEM);

    // operand splits
    split_kernel<<<(BL * D_MODEL + 255) / 256, 256>>>(x, xh, xl, BL * D_MODEL);
    split_kernel<<<(D_IN_PROJ * D_MODEL + 255) / 256, 256>>>(in_proj_w, w1h, w1l, D_IN_PROJ * D_MODEL);
    split_kernel<<<(D_MODEL * D_INNER + 255) / 256, 256>>>(out_proj_w, w2h, w2l, D_MODEL * D_INNER);

    // 1) in_proj: zx = x @ in_proj_w^T
    gemm_mma<<<dim3((D_IN_PROJ + 127) / 128, BL / 128), 256, GSMEM>>>(
        xh, xl, w1h, w1l, zx, nullptr, BL, D_IN_PROJ, D_MODEL);

    // 2) conv + silu
    conv_silu_kernel<<<dim3(CONV_DIM / 256, BL), 256>>>(conv_w, conv_b);

    // 3) dt / dA
    dt_kernel<<<(BL * NHEADS) / 256, 256>>>(dt_bias, A_log);

    // 4) scan
    scan_kernel<<<BATCH * NHEADS, 256>>>(Dv);

    // 5) gate + RMSNorm + split
    gatenorm_kernel<<<BL, 256>>>(norm_w);

    // 6) out_proj + residual
    gemm_mma<<<dim3(D_MODEL / 128, BL / 128), 256, GSMEM>>>(
        nh, nl, w2h, w2l, out, x, BL, D_MODEL, D_INNER);
}

// round 5
// speedup vs baseline: 3.0371x; 1.9679x over previous
#include <cuda_runtime.h>
#include <cuda_bf16.h>
#include <cstdint>

typedef unsigned long long ull;

#define D_MODEL   1024
#define D_STATE   128
#define D_INNER   2048
#define NHEADS    32
#define HEADDIM   64
#define CONV_DIM  2304
#define D_IN_PROJ 4384
#define SEQLEN    2048
#define BATCH     2
#define BL        (BATCH * SEQLEN)   // 4096

// ---------------- device scratch ----------------
__device__ float g_zx[(size_t)BL * D_IN_PROJ];
__device__ float g_xconv[(size_t)BL * CONV_DIM];
__device__ float g_dtp[(size_t)BL * NHEADS];
__device__ float g_dA[(size_t)BL * NHEADS];
__device__ float g_y[(size_t)BL * D_INNER];
__device__ __nv_bfloat16 g_xhb[(size_t)BL * D_MODEL];
__device__ __nv_bfloat16 g_xlb[(size_t)BL * D_MODEL];
__device__ __nv_bfloat16 g_w1h[(size_t)D_IN_PROJ * D_MODEL];
__device__ __nv_bfloat16 g_w1l[(size_t)D_IN_PROJ * D_MODEL];
__device__ __nv_bfloat16 g_w2h[(size_t)D_MODEL * D_INNER];
__device__ __nv_bfloat16 g_w2l[(size_t)D_MODEL * D_INNER];
__device__ __nv_bfloat16 g_nh[(size_t)BL * D_INNER];
__device__ __nv_bfloat16 g_nl[(size_t)BL * D_INNER];

// ---------------- PTX helpers ----------------
__device__ __forceinline__ uint32_t smem_u32(const void* p) {
    return (uint32_t)__cvta_generic_to_shared(p);
}
__device__ __forceinline__ void cp_async16(uint32_t dst, const void* src, int nbytes) {
    asm volatile("cp.async.cg.shared.global [%0], [%1], 16, %2;" :: "r"(dst), "l"(src), "r"(nbytes) : "memory");
}
__device__ __forceinline__ void cp_async4(uint32_t dst, const void* src) {
    asm volatile("cp.async.ca.shared.global [%0], [%1], 4;" :: "r"(dst), "l"(src) : "memory");
}
__device__ __forceinline__ void cp_commit() { asm volatile("cp.async.commit_group;" ::: "memory"); }
template<int N> __device__ __forceinline__ void cp_wait() { asm volatile("cp.async.wait_group %0;" :: "n"(N) : "memory"); }

__device__ __forceinline__ void ldsm4(uint32_t* r, uint32_t addr) {
    asm volatile("ldmatrix.sync.aligned.m8n8.x4.shared.b16 {%0,%1,%2,%3}, [%4];"
        : "=r"(r[0]), "=r"(r[1]), "=r"(r[2]), "=r"(r[3]) : "r"(addr));
}
__device__ __forceinline__ void mma16816(float* d, const uint32_t* a, const uint32_t* b) {
    asm volatile("mma.sync.aligned.m16n8k16.row.col.f32.bf16.bf16.f32 "
        "{%0,%1,%2,%3}, {%4,%5,%6,%7}, {%8,%9}, {%0,%1,%2,%3};"
        : "+f"(d[0]), "+f"(d[1]), "+f"(d[2]), "+f"(d[3])
        : "r"(a[0]), "r"(a[1]), "r"(a[2]), "r"(a[3]), "r"(b[0]), "r"(b[1]));
}

// =====================================================================
// bf16 3-term-split GEMM (unchanged from R4 passing kernel)
// =====================================================================
#define ROW_B   80
#define TILE_B  (128 * ROW_B)
#define STAGE_B (4 * TILE_B)
#define GSMEM   (2 * STAGE_B)

__global__ __launch_bounds__(256, 1) void gemm_mma(
    const __nv_bfloat16* __restrict__ Ah, const __nv_bfloat16* __restrict__ Al,
    const __nv_bfloat16* __restrict__ Bh, const __nv_bfloat16* __restrict__ Bl,
    float* __restrict__ C, const float* __restrict__ resid,
    int M, int N, int K)
{
    extern __shared__ char sm[];
    const uint32_t smb = smem_u32(sm);
    const int tid  = threadIdx.x;
    const int wid  = tid >> 5;
    const int lane = tid & 31;
    const int bm = blockIdx.y * 128;
    const int bn = blockIdx.x * 128;
    const int wm = (wid & 3) * 32;
    const int wn = (wid >> 2) * 64;

    const __nv_bfloat16* srcs[4] = {Ah, Al, Bh, Bl};

    auto stage = [&](int it, int buf) {
        const int k0 = it * 32;
#pragma unroll
        for (int i = 0; i < 8; i++) {
            int f = tid + i * 256;
            int tsel = f >> 9;
            int c = f & 511;
            int r = c >> 2;
            int cc = c & 3;
            uint32_t dst = smb + buf * STAGE_B + tsel * TILE_B + r * ROW_B + cc * 16;
            int row = (tsel < 2) ? (bm + r) : (bn + r);
            int nb = 16;
            if (tsel >= 2 && row >= N) { row = bn; nb = 0; }
            cp_async16(dst, srcs[tsel] + (size_t)row * K + k0 + cc * 8, nb);
        }
    };

    const int jj = lane >> 3;
    const int lr = lane & 7;
    const int aRow = (jj & 1) * 8 + lr;
    const int aColB = (jj >> 1) * 16;
    const int bRow = (jj >> 1) * 8 + lr;
    const int bColB = (jj & 1) * 16;

    float acc[2][8][4];
#pragma unroll
    for (int mt = 0; mt < 2; mt++)
#pragma unroll
        for (int j = 0; j < 8; j++)
#pragma unroll
            for (int e = 0; e < 4; e++) acc[mt][j][e] = 0.f;

    const int NIT = K >> 5;
    stage(0, 0);
    cp_commit();

    for (int it = 0; it < NIT; it++) {
        const int buf = it & 1;
        if (it + 1 < NIT) { stage(it + 1, buf ^ 1); cp_commit(); cp_wait<1>(); }
        else              { cp_wait<0>(); }
        __syncthreads();

        const uint32_t ab  = smb + buf * STAGE_B;
        const uint32_t alb = ab + TILE_B;
        const uint32_t bhb = ab + 2 * TILE_B;
        const uint32_t blb = ab + 3 * TILE_B;

#pragma unroll
        for (int ks = 0; ks < 2; ks++) {
            uint32_t ah[2][4], alf[2][4], bh[4][4], blf[4][4];
#pragma unroll
            for (int mt = 0; mt < 2; mt++) {
                uint32_t off = (uint32_t)((wm + mt * 16 + aRow) * ROW_B + ks * 32 + aColB);
                ldsm4(ah[mt],  ab  + off);
                ldsm4(alf[mt], alb + off);
            }
#pragma unroll
            for (int pn = 0; pn < 4; pn++) {
                uint32_t off = (uint32_t)((wn + pn * 16 + bRow) * ROW_B + ks * 32 + bColB);
                ldsm4(bh[pn],  bhb + off);
                ldsm4(blf[pn], blb + off);
            }
#pragma unroll
            for (int mt = 0; mt < 2; mt++)
#pragma unroll
                for (int j = 0; j < 8; j++) {
                    const uint32_t* bf = bh[j >> 1] + (j & 1) * 2;
                    const uint32_t* bl2 = blf[j >> 1] + (j & 1) * 2;
                    mma16816(acc[mt][j], ah[mt],  bf);
                    mma16816(acc[mt][j], alf[mt], bf);
                    mma16816(acc[mt][j], ah[mt],  bl2);
                }
        }
        __syncthreads();
    }

    const int r0 = bm + wm + (lane >> 2);
#pragma unroll
    for (int mt = 0; mt < 2; mt++) {
#pragma unroll
        for (int j = 0; j < 8; j++) {
            int col = bn + wn + (j >> 1) * 16 + (j & 1) * 8 + (lane & 3) * 2;
            if (col < N) {
                int r1 = r0 + mt * 16;
                int r2 = r1 + 8;
                float2 v1 = make_float2(acc[mt][j][0], acc[mt][j][1]);
                float2 v2 = make_float2(acc[mt][j][2], acc[mt][j][3]);
                if (resid) {
                    float2 q1 = *(const float2*)(resid + (size_t)r1 * N + col);
                    float2 q2 = *(const float2*)(resid + (size_t)r2 * N + col);
                    v1.x += q1.x; v1.y += q1.y; v2.x += q2.x; v2.y += q2.y;
                }
                *(float2*)(C + (size_t)r1 * N + col) = v1;
                *(float2*)(C + (size_t)r2 * N + col) = v2;
            }
        }
    }
}

// =====================================================================
__global__ __launch_bounds__(256) void split_kernel(
    const float* __restrict__ src, __nv_bfloat16* __restrict__ hi,
    __nv_bfloat16* __restrict__ lo, int n)
{
    int i = blockIdx.x * 256 + threadIdx.x;
    if (i < n) {
        float v = src[i];
        __nv_bfloat16 h = __float2bfloat16_rn(v);
        hi[i] = h;
        lo[i] = __float2bfloat16_rn(v - __bfloat162float(h));
    }
}

__global__ __launch_bounds__(256) void conv_silu_kernel(
    const float* __restrict__ cw, const float* __restrict__ cb)
{
    int c = blockIdx.x * 256 + threadIdx.x;
    int row = blockIdx.y;
    int t = row & (SEQLEN - 1);
    float4 w = *(const float4*)(cw + c * 4);
    const float* wv = (const float*)&w;
    const float* col = g_zx + (size_t)row * D_IN_PROJ + D_INNER + c;
    float s = 0.f;
#pragma unroll
    for (int j = 0; j < 4; j++) {
        int tt = t - 3 + j;
        if (tt >= 0) s = fmaf(wv[j], col[(j - 3) * D_IN_PROJ], s);
    }
    s += cb[c];
    g_xconv[(size_t)row * CONV_DIM + c] = s / (1.f + expf(-s));
}

__global__ __launch_bounds__(256) void dt_kernel(
    const float* __restrict__ dt_bias, const float* __restrict__ A_log)
{
    int idx = blockIdx.x * 256 + threadIdx.x;
    int row = idx >> 5;
    int hh = idx & 31;
    float v = g_zx[(size_t)row * D_IN_PROJ + (D_INNER + CONV_DIM) + hh] + dt_bias[hh];
    float sp = (v > 20.f) ? v : log1pf(expf(v));
    g_dtp[idx] = sp;
    g_dA[idx] = expf(-expf(A_log[hh]) * sp);
}

// =====================================================================
// selective scan v2: 128 blocks = (b, h, p-half). 128 threads.
// Thread (pg,ng) owns 4 p x 8 n of state. cp.async 4-deep ring,
// 2 timesteps per iteration, distance-6-steps prefetch.
// =====================================================================
__device__ __forceinline__ ull f2fma(ull a, ull b, ull c) { ull d; asm("fma.rn.f32x2 %0, %1, %2, %3;" : "=l"(d) : "l"(a), "l"(b), "l"(c)); return d; }
__device__ __forceinline__ ull f2mul(ull a, ull b) { ull d; asm("mul.rn.f32x2 %0, %1, %2;" : "=l"(d) : "l"(a), "l"(b)); return d; }
__device__ __forceinline__ ull f2pack(float x) { ull d; asm("mov.b64 %0, {%1, %2};" : "=l"(d) : "f"(x), "f"(x)); return d; }
__device__ __forceinline__ float f2sum(ull a) { float lo, hi; asm("mov.b64 {%0, %1}, %2;" : "=f"(lo), "=f"(hi) : "l"(a)); return lo + hi; }

__global__ __launch_bounds__(128) void scan_kernel(const float* __restrict__ Dv)
{
    const int bx = blockIdx.x;
    const int bi = bx >> 6;           // batch
    const int h  = (bx >> 1) & 31;    // head
    const int ph = bx & 1;            // p-half (32 rows)
    const int tid = threadIdx.x;
    const int pg = tid >> 4;          // 0..7  (4 p-rows each)
    const int ng = tid & 15;          // 0..15 (8 n-values each)

    __shared__ __align__(16) float sB[4][2][128];
    __shared__ __align__(16) float sC[4][2][128];
    __shared__ __align__(16) float sxs[4][2][32];
    __shared__ __align__(16) float ssc[4][2][4];

    ull S[4][4];
#pragma unroll
    for (int p = 0; p < 4; p++)
#pragma unroll
        for (int j = 0; j < 4; j++) S[p][j] = 0ULL;

    const float Dh = Dv[h];
    const float* xcb = g_xconv + (size_t)bi * SEQLEN * CONV_DIM;
    const float* dAb = g_dA  + (size_t)bi * SEQLEN * NHEADS + h;
    const float* dtb = g_dtp + (size_t)bi * SEQLEN * NHEADS + h;
    const int xofs = h * 64 + ph * 32;

    // stage two rows (t, t+1) into ring slot pi
    auto stage2 = [&](int t, int pi) {
#pragma unroll
        for (int half = 0; half < 2; half++) {
            int c = tid + half * 128;
            if (c >= 148) break;
            int s = (c >= 74) ? 1 : 0;
            int cc = c - s * 74;
            const float* rowp = xcb + (size_t)(t + s) * CONV_DIM;
            if (cc < 32)      cp_async16(smem_u32(&sB[pi][s][cc * 4]),  rowp + D_INNER + cc * 4, 16);
            else if (cc < 64) cp_async16(smem_u32(&sC[pi][s][(cc - 32) * 4]), rowp + D_INNER + D_STATE + (cc - 32) * 4, 16);
            else if (cc < 72) cp_async16(smem_u32(&sxs[pi][s][(cc - 64) * 4]), rowp + xofs + (cc - 64) * 4, 16);
            else if (cc == 72) cp_async4(smem_u32(&ssc[pi][s][0]), dAb + (size_t)(t + s) * NHEADS);
            else               cp_async4(smem_u32(&ssc[pi][s][1]), dtb + (size_t)(t + s) * NHEADS);
        }
    };

    stage2(0, 0); cp_commit();
    stage2(2, 1); cp_commit();
    stage2(4, 2); cp_commit();
    stage2(6, 3); cp_commit();

    float* yout = g_y + (size_t)bi * SEQLEN * D_INNER + xofs + pg * 4;

    const int NITER = SEQLEN / 2;
    for (int it = 0; it < NITER; it++) {
        const int t = it * 2;
        const int pi = it & 3;
        cp_wait<3>();
        __syncthreads();

#pragma unroll
        for (int s = 0; s < 2; s++) {
            const float dAv = ssc[pi][s][0];
            const float dtv = ssc[pi][s][1];
            const float4 xs4 = *(const float4*)&sxs[pi][s][pg * 4];
            const ull dA2 = f2pack(dAv);
            const ull* Bp = (const ull*)&sB[pi][s][ng * 8];
            const ull* Cp = (const ull*)&sC[pi][s][ng * 8];
            const ull B0 = Bp[0], B1 = Bp[1], B2 = Bp[2], B3 = Bp[3];
            const ull C0 = Cp[0], C1 = Cp[1], C2 = Cp[2], C3 = Cp[3];
            float y[4];
#pragma unroll
            for (int p = 0; p < 4; p++) {
                const float xv = ((const float*)&xs4)[p];
                const ull xdt2 = f2pack(xv * dtv);
                ull a0, a1;
                S[p][0] = f2fma(dA2, S[p][0], f2mul(xdt2, B0)); a0 = f2mul(S[p][0], C0);
                S[p][1] = f2fma(dA2, S[p][1], f2mul(xdt2, B1)); a1 = f2mul(S[p][1], C1);
                S[p][2] = f2fma(dA2, S[p][2], f2mul(xdt2, B2)); a0 = f2fma(S[p][2], C2, a0);
                S[p][3] = f2fma(dA2, S[p][3], f2mul(xdt2, B3)); a1 = f2fma(S[p][3], C3, a1);
                y[p] = f2sum(a0) + f2sum(a1);
            }
#pragma unroll
            for (int o = 1; o < 16; o <<= 1) {
#pragma unroll
                for (int p = 0; p < 4; p++) y[p] += __shfl_xor_sync(0xffffffffu, y[p], o);
            }
            if (ng == 0) {
                float4 v;
                v.x = fmaf(Dh, xs4.x, y[0]);
                v.y = fmaf(Dh, xs4.y, y[1]);
                v.z = fmaf(Dh, xs4.z, y[2]);
                v.w = fmaf(Dh, xs4.w, y[3]);
                *(float4*)(yout + (size_t)(t + s) * D_INNER) = v;
            }
        }
        __syncthreads();
        if (t + 8 < SEQLEN) stage2(t + 8, pi);
        cp_commit();
    }
}

// =====================================================================
__global__ __launch_bounds__(256) void gatenorm_kernel(const float* __restrict__ nw)
{
    int row = blockIdx.x;
    int tid = threadIdx.x;
    const float* yr = g_y + (size_t)row * D_INNER;
    const float* zr = g_zx + (size_t)row * D_IN_PROJ;
    float v[8];
    float ss = 0.f;
#pragma unroll
    for (int i = 0; i < 8; i++) {
        int c = tid + i * 256;
        float z = zr[c];
        float val = yr[c] * (z / (1.f + expf(-z)));
        v[i] = val;
        ss = fmaf(val, val, ss);
    }
#pragma unroll
    for (int o = 16; o; o >>= 1) ss += __shfl_xor_sync(0xffffffffu, ss, o);
    __shared__ float red[8];
    if ((tid & 31) == 0) red[tid >> 5] = ss;
    __syncthreads();
    float tot = red[0] + red[1] + red[2] + red[3] + red[4] + red[5] + red[6] + red[7];
    float scale = rsqrtf(tot * (1.0f / 2048.0f) + 1e-5f);
#pragma unroll
    for (int i = 0; i < 8; i++) {
        int c = tid + i * 256;
        float val = v[i] * scale * nw[c];
        __nv_bfloat16 h = __float2bfloat16_rn(val);
        g_nh[(size_t)row * D_INNER + c] = h;
        g_nl[(size_t)row * D_INNER + c] = __float2bfloat16_rn(val - __bfloat162float(h));
    }
}

// =====================================================================
extern "C" void kernel_launch(void* const* d_in, const int* in_sizes, int n_in,
                              void* d_out, int out_size)
{
    const float* x          = (const float*)d_in[0];
    const float* in_proj_w  = (const float*)d_in[1];
    const float* conv_w     = (const float*)d_in[2];
    const float* conv_b     = (const float*)d_in[3];
    const float* dt_bias    = (const float*)d_in[4];
    const float* A_log      = (const float*)d_in[5];
    const float* Dv         = (const float*)d_in[6];
    const float* norm_w     = (const float*)d_in[7];
    const float* out_proj_w = (const float*)d_in[8];
    float* out = (float*)d_out;

    float *zx;
    __nv_bfloat16 *xh, *xl, *w1h, *w1l, *w2h, *w2l, *nh, *nl;
    cudaGetSymbolAddress((void**)&zx, g_zx);
    cudaGetSymbolAddress((void**)&xh, g_xhb);
    cudaGetSymbolAddress((void**)&xl, g_xlb);
    cudaGetSymbolAddress((void**)&w1h, g_w1h);
    cudaGetSymbolAddress((void**)&w1l, g_w1l);
    cudaGetSymbolAddress((void**)&w2h, g_w2h);
    cudaGetSymbolAddress((void**)&w2l, g_w2l);
    cudaGetSymbolAddress((void**)&nh, g_nh);
    cudaGetSymbolAddress((void**)&nl, g_nl);

    cudaFuncSetAttribute(gemm_mma, cudaFuncAttributeMaxDynamicSharedMemorySize, GSMEM);

    split_kernel<<<(BL * D_MODEL + 255) / 256, 256>>>(x, xh, xl, BL * D_MODEL);
    split_kernel<<<(D_IN_PROJ * D_MODEL + 255) / 256, 256>>>(in_proj_w, w1h, w1l, D_IN_PROJ * D_MODEL);
    split_kernel<<<(D_MODEL * D_INNER + 255) / 256, 256>>>(out_proj_w, w2h, w2l, D_MODEL * D_INNER);

    gemm_mma<<<dim3((D_IN_PROJ + 127) / 128, BL / 128), 256, GSMEM>>>(
        xh, xl, w1h, w1l, zx, nullptr, BL, D_IN_PROJ, D_MODEL);

    conv_silu_kernel<<<dim3(CONV_DIM / 256, BL), 256>>>(conv_w, conv_b);
    dt_kernel<<<(BL * NHEADS) / 256, 256>>>(dt_bias, A_log);

    scan_kernel<<<BATCH * NHEADS * 2, 128>>>(Dv);

    gatenorm_kernel<<<BL, 256>>>(norm_w);

    gemm_mma<<<dim3(D_MODEL / 128, BL / 128), 256, GSMEM>>>(
        nh, nl, w2h, w2l, out, x, BL, D_MODEL, D_INNER);
}

// round 6
// speedup vs baseline: 3.2190x; 1.0599x over previous
#include <cuda_runtime.h>
#include <cuda_bf16.h>
#include <cstdint>

typedef unsigned long long ull;

#define D_MODEL   1024
#define D_STATE   128
#define D_INNER   2048
#define NHEADS    32
#define HEADDIM   64
#define CONV_DIM  2304
#define D_IN_PROJ 4384
#define SEQLEN    2048
#define BATCH     2
#define BL        (BATCH * SEQLEN)   // 4096

// ---------------- device scratch ----------------
__device__ float g_zx[(size_t)BL * D_IN_PROJ];
__device__ float g_xconv[(size_t)BL * CONV_DIM];
__device__ float g_dtp[(size_t)BL * NHEADS];
__device__ float g_dA[(size_t)BL * NHEADS];
__device__ float g_y[(size_t)BL * D_INNER];
__device__ __nv_bfloat16 g_xhb[(size_t)BL * D_MODEL];
__device__ __nv_bfloat16 g_xlb[(size_t)BL * D_MODEL];
__device__ __nv_bfloat16 g_w1h[(size_t)D_IN_PROJ * D_MODEL];
__device__ __nv_bfloat16 g_w1l[(size_t)D_IN_PROJ * D_MODEL];
__device__ __nv_bfloat16 g_w2h[(size_t)D_MODEL * D_INNER];
__device__ __nv_bfloat16 g_w2l[(size_t)D_MODEL * D_INNER];
__device__ __nv_bfloat16 g_nh[(size_t)BL * D_INNER];
__device__ __nv_bfloat16 g_nl[(size_t)BL * D_INNER];

// ---------------- PTX helpers ----------------
__device__ __forceinline__ uint32_t smem_u32(const void* p) {
    return (uint32_t)__cvta_generic_to_shared(p);
}
__device__ __forceinline__ void cp_async16(uint32_t dst, const void* src, int nbytes) {
    asm volatile("cp.async.cg.shared.global [%0], [%1], 16, %2;" :: "r"(dst), "l"(src), "r"(nbytes) : "memory");
}
__device__ __forceinline__ void cp_async4(uint32_t dst, const void* src) {
    asm volatile("cp.async.ca.shared.global [%0], [%1], 4;" :: "r"(dst), "l"(src) : "memory");
}
__device__ __forceinline__ void cp_commit() { asm volatile("cp.async.commit_group;" ::: "memory"); }
template<int N> __device__ __forceinline__ void cp_wait() { asm volatile("cp.async.wait_group %0;" :: "n"(N) : "memory"); }

__device__ __forceinline__ void ldsm4(uint32_t* r, uint32_t addr) {
    asm volatile("ldmatrix.sync.aligned.m8n8.x4.shared.b16 {%0,%1,%2,%3}, [%4];"
        : "=r"(r[0]), "=r"(r[1]), "=r"(r[2]), "=r"(r[3]) : "r"(addr));
}
__device__ __forceinline__ void mma16816(float* d, const uint32_t* a, const uint32_t* b) {
    asm volatile("mma.sync.aligned.m16n8k16.row.col.f32.bf16.bf16.f32 "
        "{%0,%1,%2,%3}, {%4,%5,%6,%7}, {%8,%9}, {%0,%1,%2,%3};"
        : "+f"(d[0]), "+f"(d[1]), "+f"(d[2]), "+f"(d[3])
        : "r"(a[0]), "r"(a[1]), "r"(a[2]), "r"(a[3]), "r"(b[0]), "r"(b[1]));
}

// =====================================================================
// bf16 3-term-split GEMM, 3-stage cp.async pipeline
// =====================================================================
#define ROW_B   80
#define TILE_B  (128 * ROW_B)
#define STAGE_B (4 * TILE_B)        // 40960
#define GSMEM   (3 * STAGE_B)       // 122880

__global__ __launch_bounds__(256, 1) void gemm_mma(
    const __nv_bfloat16* __restrict__ Ah, const __nv_bfloat16* __restrict__ Al,
    const __nv_bfloat16* __restrict__ Bh, const __nv_bfloat16* __restrict__ Bl,
    float* __restrict__ C, const float* __restrict__ resid,
    int M, int N, int K)
{
    extern __shared__ char sm[];
    const uint32_t smb = smem_u32(sm);
    const int tid  = threadIdx.x;
    const int wid  = tid >> 5;
    const int lane = tid & 31;
    const int bm = blockIdx.y * 128;
    const int bn = blockIdx.x * 128;
    const int wm = (wid & 3) * 32;
    const int wn = (wid >> 2) * 64;

    const __nv_bfloat16* srcs[4] = {Ah, Al, Bh, Bl};

    auto stage = [&](int it, int buf) {
        const int k0 = it * 32;
#pragma unroll
        for (int i = 0; i < 8; i++) {
            int f = tid + i * 256;
            int tsel = f >> 9;
            int c = f & 511;
            int r = c >> 2;
            int cc = c & 3;
            uint32_t dst = smb + buf * STAGE_B + tsel * TILE_B + r * ROW_B + cc * 16;
            int row = (tsel < 2) ? (bm + r) : (bn + r);
            int nb = 16;
            if (tsel >= 2 && row >= N) { row = bn; nb = 0; }
            cp_async16(dst, srcs[tsel] + (size_t)row * K + k0 + cc * 8, nb);
        }
    };

    const int jj = lane >> 3;
    const int lr = lane & 7;
    const int aRow = (jj & 1) * 8 + lr;
    const int aColB = (jj >> 1) * 16;
    const int bRow = (jj >> 1) * 8 + lr;
    const int bColB = (jj & 1) * 16;

    float acc[2][8][4];
#pragma unroll
    for (int mt = 0; mt < 2; mt++)
#pragma unroll
        for (int j = 0; j < 8; j++)
#pragma unroll
            for (int e = 0; e < 4; e++) acc[mt][j][e] = 0.f;

    const int NIT = K >> 5;
    stage(0, 0); cp_commit();
    stage(1, 1); cp_commit();

    for (int it = 0; it < NIT; it++) {
        const int buf = it % 3;
        if (it + 2 < NIT) stage(it + 2, (it + 2) % 3);
        cp_commit();
        cp_wait<2>();
        __syncthreads();

        const uint32_t ab  = smb + buf * STAGE_B;
        const uint32_t alb = ab + TILE_B;
        const uint32_t bhb = ab + 2 * TILE_B;
        const uint32_t blb = ab + 3 * TILE_B;

#pragma unroll
        for (int ks = 0; ks < 2; ks++) {
            uint32_t ah[2][4], alf[2][4], bh[4][4], blf[4][4];
#pragma unroll
            for (int mt = 0; mt < 2; mt++) {
                uint32_t off = (uint32_t)((wm + mt * 16 + aRow) * ROW_B + ks * 32 + aColB);
                ldsm4(ah[mt],  ab  + off);
                ldsm4(alf[mt], alb + off);
            }
#pragma unroll
            for (int pn = 0; pn < 4; pn++) {
                uint32_t off = (uint32_t)((wn + pn * 16 + bRow) * ROW_B + ks * 32 + bColB);
                ldsm4(bh[pn],  bhb + off);
                ldsm4(blf[pn], blb + off);
            }
#pragma unroll
            for (int mt = 0; mt < 2; mt++)
#pragma unroll
                for (int j = 0; j < 8; j++) {
                    const uint32_t* bf  = bh[j >> 1] + (j & 1) * 2;
                    const uint32_t* bl2 = blf[j >> 1] + (j & 1) * 2;
                    mma16816(acc[mt][j], ah[mt],  bf);
                    mma16816(acc[mt][j], alf[mt], bf);
                    mma16816(acc[mt][j], ah[mt],  bl2);
                }
        }
        __syncthreads();
    }

    const int r0 = bm + wm + (lane >> 2);
#pragma unroll
    for (int mt = 0; mt < 2; mt++) {
#pragma unroll
        for (int j = 0; j < 8; j++) {
            int col = bn + wn + (j >> 1) * 16 + (j & 1) * 8 + (lane & 3) * 2;
            if (col < N) {
                int r1 = r0 + mt * 16;
                int r2 = r1 + 8;
                float2 v1 = make_float2(acc[mt][j][0], acc[mt][j][1]);
                float2 v2 = make_float2(acc[mt][j][2], acc[mt][j][3]);
                if (resid) {
                    float2 q1 = *(const float2*)(resid + (size_t)r1 * N + col);
                    float2 q2 = *(const float2*)(resid + (size_t)r2 * N + col);
                    v1.x += q1.x; v1.y += q1.y; v2.x += q2.x; v2.y += q2.y;
                }
                *(float2*)(C + (size_t)r1 * N + col) = v1;
                *(float2*)(C + (size_t)r2 * N + col) = v2;
            }
        }
    }
}

// =====================================================================
__global__ __launch_bounds__(256) void split_kernel(
    const float* __restrict__ src, __nv_bfloat16* __restrict__ hi,
    __nv_bfloat16* __restrict__ lo, int n)
{
    int i = blockIdx.x * 256 + threadIdx.x;
    if (i < n) {
        float v = src[i];
        __nv_bfloat16 h = __float2bfloat16_rn(v);
        hi[i] = h;
        lo[i] = __float2bfloat16_rn(v - __bfloat162float(h));
    }
}

__global__ __launch_bounds__(256) void conv_silu_kernel(
    const float* __restrict__ cw, const float* __restrict__ cb)
{
    int c = blockIdx.x * 256 + threadIdx.x;
    int row = blockIdx.y;
    int t = row & (SEQLEN - 1);
    float4 w = *(const float4*)(cw + c * 4);
    const float* wv = (const float*)&w;
    const float* col = g_zx + (size_t)row * D_IN_PROJ + D_INNER + c;
    float s = 0.f;
#pragma unroll
    for (int j = 0; j < 4; j++) {
        int tt = t - 3 + j;
        if (tt >= 0) s = fmaf(wv[j], col[(j - 3) * D_IN_PROJ], s);
    }
    s += cb[c];
    g_xconv[(size_t)row * CONV_DIM + c] = s / (1.f + expf(-s));
}

__global__ __launch_bounds__(256) void dt_kernel(
    const float* __restrict__ dt_bias, const float* __restrict__ A_log)
{
    int idx = blockIdx.x * 256 + threadIdx.x;
    int row = idx >> 5;
    int hh = idx & 31;
    float v = g_zx[(size_t)row * D_IN_PROJ + (D_INNER + CONV_DIM) + hh] + dt_bias[hh];
    float sp = (v > 20.f) ? v : log1pf(expf(v));
    g_dtp[idx] = sp;
    g_dA[idx] = expf(-expf(A_log[hh]) * sp);
}

// =====================================================================
// selective scan v3: 128 blocks = (b, h, p-half), 128 threads.
// 4 ring slots x 4 timesteps. y-reduction deferred and batched over
// 4 steps (16 independent butterfly chains -> latency amortized).
// =====================================================================
__device__ __forceinline__ ull f2fma(ull a, ull b, ull c) { ull d; asm("fma.rn.f32x2 %0, %1, %2, %3;" : "=l"(d) : "l"(a), "l"(b), "l"(c)); return d; }
__device__ __forceinline__ ull f2mul(ull a, ull b) { ull d; asm("mul.rn.f32x2 %0, %1, %2;" : "=l"(d) : "l"(a), "l"(b)); return d; }
__device__ __forceinline__ ull f2pack(float x) { ull d; asm("mov.b64 %0, {%1, %2};" : "=l"(d) : "f"(x), "f"(x)); return d; }
__device__ __forceinline__ float f2sum(ull a) { float lo, hi; asm("mov.b64 {%0, %1}, %2;" : "=f"(lo), "=f"(hi) : "l"(a)); return lo + hi; }

__global__ __launch_bounds__(128) void scan_kernel(const float* __restrict__ Dv)
{
    const int bx = blockIdx.x;
    const int bi = bx >> 6;
    const int h  = (bx >> 1) & 31;
    const int ph = bx & 1;
    const int tid = threadIdx.x;
    const int pg = tid >> 4;          // 0..7, 4 p-rows each
    const int ng = tid & 15;          // 0..15, 8 n each

    __shared__ __align__(16) float sB[4][4][128];
    __shared__ __align__(16) float sC[4][4][128];
    __shared__ __align__(16) float sxs[4][4][32];
    __shared__ __align__(16) float ssc[4][4][4];

    ull S[4][4];
#pragma unroll
    for (int p = 0; p < 4; p++)
#pragma unroll
        for (int j = 0; j < 4; j++) S[p][j] = 0ULL;

    const float Dh = Dv[h];
    const float* xcb = g_xconv + (size_t)bi * SEQLEN * CONV_DIM;
    const float* dAb = g_dA  + (size_t)bi * SEQLEN * NHEADS + h;
    const float* dtb = g_dtp + (size_t)bi * SEQLEN * NHEADS + h;
    const int xofs = h * 64 + ph * 32;

    // stage 4 rows (t..t+3) into ring slot pi: 74 cp ops per row
    auto stage4 = [&](int t, int pi) {
#pragma unroll
        for (int k = 0; k < 3; k++) {
            int c = tid + k * 128;
            if (c >= 296) break;
            int s = c / 74;
            int cc = c - s * 74;
            const float* rowp = xcb + (size_t)(t + s) * CONV_DIM;
            if (cc < 32)       cp_async16(smem_u32(&sB[pi][s][cc * 4]),  rowp + D_INNER + cc * 4, 16);
            else if (cc < 64)  cp_async16(smem_u32(&sC[pi][s][(cc - 32) * 4]), rowp + D_INNER + D_STATE + (cc - 32) * 4, 16);
            else if (cc < 72)  cp_async16(smem_u32(&sxs[pi][s][(cc - 64) * 4]), rowp + xofs + (cc - 64) * 4, 16);
            else if (cc == 72) cp_async4(smem_u32(&ssc[pi][s][0]), dAb + (size_t)(t + s) * NHEADS);
            else               cp_async4(smem_u32(&ssc[pi][s][1]), dtb + (size_t)(t + s) * NHEADS);
        }
    };

    stage4(0, 0);  cp_commit();
    stage4(4, 1);  cp_commit();
    stage4(8, 2);  cp_commit();
    stage4(12, 3); cp_commit();

    float* yout = g_y + (size_t)bi * SEQLEN * D_INNER + xofs + pg * 4;

    const int NITER = SEQLEN / 4;
    for (int it = 0; it < NITER; it++) {
        const int t = it * 4;
        const int pi = it & 3;
        cp_wait<3>();
        __syncthreads();

        float yv[4][4];   // [p][s]
#pragma unroll
        for (int s = 0; s < 4; s++) {
            const float dAv = ssc[pi][s][0];
            const float dtv = ssc[pi][s][1];
            const float4 xs4 = *(const float4*)&sxs[pi][s][pg * 4];
            const ull dA2 = f2pack(dAv);
            const ull* Bp = (const ull*)&sB[pi][s][ng * 8];
            const ull* Cp = (const ull*)&sC[pi][s][ng * 8];
            const ull B0 = Bp[0], B1 = Bp[1], B2 = Bp[2], B3 = Bp[3];
            const ull C0 = Cp[0], C1 = Cp[1], C2 = Cp[2], C3 = Cp[3];
#pragma unroll
            for (int p = 0; p < 4; p++) {
                const float xv = ((const float*)&xs4)[p];
                const ull xdt2 = f2pack(xv * dtv);
                ull a0, a1;
                S[p][0] = f2fma(dA2, S[p][0], f2mul(xdt2, B0)); a0 = f2mul(S[p][0], C0);
                S[p][1] = f2fma(dA2, S[p][1], f2mul(xdt2, B1)); a1 = f2mul(S[p][1], C1);
                S[p][2] = f2fma(dA2, S[p][2], f2mul(xdt2, B2)); a0 = f2fma(S[p][2], C2, a0);
                S[p][3] = f2fma(dA2, S[p][3], f2mul(xdt2, B3)); a1 = f2fma(S[p][3], C3, a1);
                yv[p][s] = f2sum(a0) + f2sum(a1);
            }
        }

        // batched butterfly reduction over 16 n-lanes (16 independent chains)
#pragma unroll
        for (int o = 1; o < 16; o <<= 1) {
#pragma unroll
            for (int p = 0; p < 4; p++)
#pragma unroll
                for (int s = 0; s < 4; s++)
                    yv[p][s] += __shfl_xor_sync(0xffffffffu, yv[p][s], o);
        }
        if (ng == 0) {
#pragma unroll
            for (int s = 0; s < 4; s++) {
                const float4 xs4 = *(const float4*)&sxs[pi][s][pg * 4];
                float4 v;
                v.x = fmaf(Dh, xs4.x, yv[0][s]);
                v.y = fmaf(Dh, xs4.y, yv[1][s]);
                v.z = fmaf(Dh, xs4.z, yv[2][s]);
                v.w = fmaf(Dh, xs4.w, yv[3][s]);
                *(float4*)(yout + (size_t)(t + s) * D_INNER) = v;
            }
        }
        __syncthreads();
        if (t + 16 < SEQLEN) stage4(t + 16, pi);
        cp_commit();
    }
}

// =====================================================================
__global__ __launch_bounds__(256) void gatenorm_kernel(const float* __restrict__ nw)
{
    int row = blockIdx.x;
    int tid = threadIdx.x;
    const float* yr = g_y + (size_t)row * D_INNER;
    const float* zr = g_zx + (size_t)row * D_IN_PROJ;
    float v[8];
    float ss = 0.f;
#pragma unroll
    for (int i = 0; i < 8; i++) {
        int c = tid + i * 256;
        float z = zr[c];
        float val = yr[c] * (z / (1.f + expf(-z)));
        v[i] = val;
        ss = fmaf(val, val, ss);
    }
#pragma unroll
    for (int o = 16; o; o >>= 1) ss += __shfl_xor_sync(0xffffffffu, ss, o);
    __shared__ float red[8];
    if ((tid & 31) == 0) red[tid >> 5] = ss;
    __syncthreads();
    float tot = red[0] + red[1] + red[2] + red[3] + red[4] + red[5] + red[6] + red[7];
    float scale = rsqrtf(tot * (1.0f / 2048.0f) + 1e-5f);
#pragma unroll
    for (int i = 0; i < 8; i++) {
        int c = tid + i * 256;
        float val = v[i] * scale * nw[c];
        __nv_bfloat16 h = __float2bfloat16_rn(val);
        g_nh[(size_t)row * D_INNER + c] = h;
        g_nl[(size_t)row * D_INNER + c] = __float2bfloat16_rn(val - __bfloat162float(h));
    }
}

// =====================================================================
extern "C" void kernel_launch(void* const* d_in, const int* in_sizes, int n_in,
                              void* d_out, int out_size)
{
    const float* x          = (const float*)d_in[0];
    const float* in_proj_w  = (const float*)d_in[1];
    const float* conv_w     = (const float*)d_in[2];
    const float* conv_b     = (const float*)d_in[3];
    const float* dt_bias    = (const float*)d_in[4];
    const float* A_log      = (const float*)d_in[5];
    const float* Dv         = (const float*)d_in[6];
    const float* norm_w     = (const float*)d_in[7];
    const float* out_proj_w = (const float*)d_in[8];
    float* out = (float*)d_out;

    float *zx;
    __nv_bfloat16 *xh, *xl, *w1h, *w1l, *w2h, *w2l, *nh, *nl;
    cudaGetSymbolAddress((void**)&zx, g_zx);
    cudaGetSymbolAddress((void**)&xh, g_xhb);
    cudaGetSymbolAddress((void**)&xl, g_xlb);
    cudaGetSymbolAddress((void**)&w1h, g_w1h);
    cudaGetSymbolAddress((void**)&w1l, g_w1l);
    cudaGetSymbolAddress((void**)&w2h, g_w2h);
    cudaGetSymbolAddress((void**)&w2l, g_w2l);
    cudaGetSymbolAddress((void**)&nh, g_nh);
    cudaGetSymbolAddress((void**)&nl, g_nl);

    cudaFuncSetAttribute(gemm_mma, cudaFuncAttributeMaxDynamicSharedMemorySize, GSMEM);

    split_kernel<<<(BL * D_MODEL + 255) / 256, 256>>>(x, xh, xl, BL * D_MODEL);
    split_kernel<<<(D_IN_PROJ * D_MODEL + 255) / 256, 256>>>(in_proj_w, w1h, w1l, D_IN_PROJ * D_MODEL);
    split_kernel<<<(D_MODEL * D_INNER + 255) / 256, 256>>>(out_proj_w, w2h, w2l, D_MODEL * D_INNER);

    gemm_mma<<<dim3((D_IN_PROJ + 127) / 128, BL / 128), 256, GSMEM>>>(
        xh, xl, w1h, w1l, zx, nullptr, BL, D_IN_PROJ, D_MODEL);

    conv_silu_kernel<<<dim3(CONV_DIM / 256, BL), 256>>>(conv_w, conv_b);
    dt_kernel<<<(BL * NHEADS) / 256, 256>>>(dt_bias, A_log);

    scan_kernel<<<BATCH * NHEADS * 2, 128>>>(Dv);

    gatenorm_kernel<<<BL, 256>>>(norm_w);

    gemm_mma<<<dim3(D_MODEL / 128, BL / 128), 256, GSMEM>>>(
        nh, nl, w2h, w2l, out, x, BL, D_MODEL, D_INNER);
}

// round 7
// speedup vs baseline: 3.5629x; 1.1068x over previous
#include <cuda_runtime.h>
#include <cuda_bf16.h>
#include <cstdint>

typedef unsigned long long ull;

#define D_MODEL   1024
#define D_STATE   128
#define D_INNER   2048
#define NHEADS    32
#define HEADDIM   64
#define CONV_DIM  2304
#define D_IN_PROJ 4384
#define SEQLEN    2048
#define BATCH     2
#define BL        (BATCH * SEQLEN)   // 4096

// ---------------- device scratch ----------------
__device__ float g_zx[(size_t)BL * D_IN_PROJ];
__device__ float g_xconv[(size_t)BL * CONV_DIM];
__device__ float g_dtp[(size_t)BL * NHEADS];
__device__ float g_dA[(size_t)BL * NHEADS];
__device__ float g_y[(size_t)BL * D_INNER];
__device__ __nv_bfloat16 g_xhb[(size_t)BL * D_MODEL];
__device__ __nv_bfloat16 g_xlb[(size_t)BL * D_MODEL];
__device__ __nv_bfloat16 g_w1h[(size_t)D_IN_PROJ * D_MODEL];
__device__ __nv_bfloat16 g_w1l[(size_t)D_IN_PROJ * D_MODEL];
__device__ __nv_bfloat16 g_w2h[(size_t)D_MODEL * D_INNER];
__device__ __nv_bfloat16 g_w2l[(size_t)D_MODEL * D_INNER];
__device__ __nv_bfloat16 g_nh[(size_t)BL * D_INNER];
__device__ __nv_bfloat16 g_nl[(size_t)BL * D_INNER];

// ---------------- PTX helpers ----------------
__device__ __forceinline__ uint32_t smem_u32(const void* p) {
    return (uint32_t)__cvta_generic_to_shared(p);
}
__device__ __forceinline__ void cp_async16(uint32_t dst, const void* src, int nbytes) {
    asm volatile("cp.async.cg.shared.global [%0], [%1], 16, %2;" :: "r"(dst), "l"(src), "r"(nbytes) : "memory");
}
__device__ __forceinline__ void cp_async4(uint32_t dst, const void* src) {
    asm volatile("cp.async.ca.shared.global [%0], [%1], 4;" :: "r"(dst), "l"(src) : "memory");
}
__device__ __forceinline__ void cp_commit() { asm volatile("cp.async.commit_group;" ::: "memory"); }
template<int N> __device__ __forceinline__ void cp_wait() { asm volatile("cp.async.wait_group %0;" :: "n"(N) : "memory"); }

__device__ __forceinline__ void ldsm4(uint32_t* r, uint32_t addr) {
    asm volatile("ldmatrix.sync.aligned.m8n8.x4.shared.b16 {%0,%1,%2,%3}, [%4];"
        : "=r"(r[0]), "=r"(r[1]), "=r"(r[2]), "=r"(r[3]) : "r"(addr));
}
__device__ __forceinline__ void mma16816(float* d, const uint32_t* a, const uint32_t* b) {
    asm volatile("mma.sync.aligned.m16n8k16.row.col.f32.bf16.bf16.f32 "
        "{%0,%1,%2,%3}, {%4,%5,%6,%7}, {%8,%9}, {%0,%1,%2,%3};"
        : "+f"(d[0]), "+f"(d[1]), "+f"(d[2]), "+f"(d[3])
        : "r"(a[0]), "r"(a[1]), "r"(a[2]), "r"(a[3]), "r"(b[0]), "r"(b[1]));
}

// =====================================================================
// bf16 3-term-split GEMM, 2-stage cp.async, 2 CTAs/SM
// =====================================================================
#define ROW_B   80
#define TILE_B  (128 * ROW_B)
#define STAGE_B (4 * TILE_B)        // 40960
#define GSMEM   (2 * STAGE_B)       // 81920

__global__ __launch_bounds__(256, 2) void gemm_mma(
    const __nv_bfloat16* __restrict__ Ah, const __nv_bfloat16* __restrict__ Al,
    const __nv_bfloat16* __restrict__ Bh, const __nv_bfloat16* __restrict__ Bl,
    float* __restrict__ C, const float* __restrict__ resid,
    int M, int N, int K)
{
    extern __shared__ char sm[];
    const uint32_t smb = smem_u32(sm);
    const int tid  = threadIdx.x;
    const int wid  = tid >> 5;
    const int lane = tid & 31;
    const int bm = blockIdx.y * 128;
    const int bn = blockIdx.x * 128;
    const int wm = (wid & 3) * 32;
    const int wn = (wid >> 2) * 64;

    const __nv_bfloat16* srcs[4] = {Ah, Al, Bh, Bl};

    auto stage = [&](int it, int buf) {
        const int k0 = it * 32;
#pragma unroll
        for (int i = 0; i < 8; i++) {
            int f = tid + i * 256;
            int tsel = f >> 9;
            int c = f & 511;
            int r = c >> 2;
            int cc = c & 3;
            uint32_t dst = smb + buf * STAGE_B + tsel * TILE_B + r * ROW_B + cc * 16;
            int row = (tsel < 2) ? (bm + r) : (bn + r);
            int nb = 16;
            if (tsel >= 2 && row >= N) { row = bn; nb = 0; }
            cp_async16(dst, srcs[tsel] + (size_t)row * K + k0 + cc * 8, nb);
        }
    };

    const int jj = lane >> 3;
    const int lr = lane & 7;
    const int aRow = (jj & 1) * 8 + lr;
    const int aColB = (jj >> 1) * 16;
    const int bRow = (jj >> 1) * 8 + lr;
    const int bColB = (jj & 1) * 16;

    float acc[2][8][4];
#pragma unroll
    for (int mt = 0; mt < 2; mt++)
#pragma unroll
        for (int j = 0; j < 8; j++)
#pragma unroll
            for (int e = 0; e < 4; e++) acc[mt][j][e] = 0.f;

    const int NIT = K >> 5;
    stage(0, 0);
    cp_commit();

    for (int it = 0; it < NIT; it++) {
        const int buf = it & 1;
        if (it + 1 < NIT) { stage(it + 1, buf ^ 1); cp_commit(); cp_wait<1>(); }
        else              { cp_wait<0>(); }
        __syncthreads();

        const uint32_t ab  = smb + buf * STAGE_B;
        const uint32_t alb = ab + TILE_B;
        const uint32_t bhb = ab + 2 * TILE_B;
        const uint32_t blb = ab + 3 * TILE_B;

#pragma unroll
        for (int ks = 0; ks < 2; ks++) {
            uint32_t ah[2][4], alf[2][4], bh[4][4], blf[4][4];
#pragma unroll
            for (int mt = 0; mt < 2; mt++) {
                uint32_t off = (uint32_t)((wm + mt * 16 + aRow) * ROW_B + ks * 32 + aColB);
                ldsm4(ah[mt],  ab  + off);
                ldsm4(alf[mt], alb + off);
            }
#pragma unroll
            for (int pn = 0; pn < 4; pn++) {
                uint32_t off = (uint32_t)((wn + pn * 16 + bRow) * ROW_B + ks * 32 + bColB);
                ldsm4(bh[pn],  bhb + off);
                ldsm4(blf[pn], blb + off);
            }
#pragma unroll
            for (int mt = 0; mt < 2; mt++)
#pragma unroll
                for (int j = 0; j < 8; j++) {
                    const uint32_t* bf  = bh[j >> 1] + (j & 1) * 2;
                    const uint32_t* bl2 = blf[j >> 1] + (j & 1) * 2;
                    mma16816(acc[mt][j], ah[mt],  bf);
                    mma16816(acc[mt][j], alf[mt], bf);
                    mma16816(acc[mt][j], ah[mt],  bl2);
                }
        }
        __syncthreads();
    }

    const int r0 = bm + wm + (lane >> 2);
#pragma unroll
    for (int mt = 0; mt < 2; mt++) {
#pragma unroll
        for (int j = 0; j < 8; j++) {
            int col = bn + wn + (j >> 1) * 16 + (j & 1) * 8 + (lane & 3) * 2;
            if (col < N) {
                int r1 = r0 + mt * 16;
                int r2 = r1 + 8;
                float2 v1 = make_float2(acc[mt][j][0], acc[mt][j][1]);
                float2 v2 = make_float2(acc[mt][j][2], acc[mt][j][3]);
                if (resid) {
                    float2 q1 = *(const float2*)(resid + (size_t)r1 * N + col);
                    float2 q2 = *(const float2*)(resid + (size_t)r2 * N + col);
                    v1.x += q1.x; v1.y += q1.y; v2.x += q2.x; v2.y += q2.y;
                }
                *(float2*)(C + (size_t)r1 * N + col) = v1;
                *(float2*)(C + (size_t)r2 * N + col) = v2;
            }
        }
    }
}

// =====================================================================
__global__ __launch_bounds__(256) void split_kernel(
    const float* __restrict__ src, __nv_bfloat16* __restrict__ hi,
    __nv_bfloat16* __restrict__ lo, int n)
{
    int i = blockIdx.x * 256 + threadIdx.x;
    if (i < n) {
        float v = src[i];
        __nv_bfloat16 h = __float2bfloat16_rn(v);
        hi[i] = h;
        lo[i] = __float2bfloat16_rn(v - __bfloat162float(h));
    }
}

__global__ __launch_bounds__(256) void conv_silu_kernel(
    const float* __restrict__ cw, const float* __restrict__ cb)
{
    int c = blockIdx.x * 256 + threadIdx.x;
    int row = blockIdx.y;
    int t = row & (SEQLEN - 1);
    float4 w = *(const float4*)(cw + c * 4);
    const float* wv = (const float*)&w;
    const float* col = g_zx + (size_t)row * D_IN_PROJ + D_INNER + c;
    float s = 0.f;
#pragma unroll
    for (int j = 0; j < 4; j++) {
        int tt = t - 3 + j;
        if (tt >= 0) s = fmaf(wv[j], col[(j - 3) * D_IN_PROJ], s);
    }
    s += cb[c];
    g_xconv[(size_t)row * CONV_DIM + c] = s / (1.f + expf(-s));
}

__global__ __launch_bounds__(256) void dt_kernel(
    const float* __restrict__ dt_bias, const float* __restrict__ A_log)
{
    int idx = blockIdx.x * 256 + threadIdx.x;
    int row = idx >> 5;
    int hh = idx & 31;
    float v = g_zx[(size_t)row * D_IN_PROJ + (D_INNER + CONV_DIM) + hh] + dt_bias[hh];
    float sp = (v > 20.f) ? v : log1pf(expf(v));
    g_dtp[idx] = sp;
    g_dA[idx] = expf(-expf(A_log[hh]) * sp);
}

// =====================================================================
// selective scan v4: 128 blocks = (b, h, p-half), 128 threads.
// Conflict-free permuted B/C reads + register double-buffer pipeline.
// =====================================================================
__device__ __forceinline__ ull f2fma(ull a, ull b, ull c) { ull d; asm("fma.rn.f32x2 %0, %1, %2, %3;" : "=l"(d) : "l"(a), "l"(b), "l"(c)); return d; }
__device__ __forceinline__ ull f2mul(ull a, ull b) { ull d; asm("mul.rn.f32x2 %0, %1, %2;" : "=l"(d) : "l"(a), "l"(b)); return d; }
__device__ __forceinline__ ull f2pack(float x) { ull d; asm("mov.b64 %0, {%1, %2};" : "=l"(d) : "f"(x), "f"(x)); return d; }
__device__ __forceinline__ float f2sum(ull a) { float lo, hi; asm("mov.b64 {%0, %1}, %2;" : "=f"(lo), "=f"(hi) : "l"(a)); return lo + hi; }

__global__ __launch_bounds__(128) void scan_kernel(const float* __restrict__ Dv)
{
    const int bx = blockIdx.x;
    const int bi = bx >> 6;
    const int h  = (bx >> 1) & 31;
    const int ph = bx & 1;
    const int tid = threadIdx.x;
    const int pg = tid >> 4;          // 0..7, 4 p-rows each
    const int ng = tid & 15;          // 0..15, 8 n each
    const int g  = ng >> 2;

    __shared__ __align__(16) float sB[4][4][128];
    __shared__ __align__(16) float sC[4][4][128];
    __shared__ __align__(16) float sxs[4][4][32];
    __shared__ __align__(16) float ssc[4][4][2];

    // conflict-free permuted float offsets: lane group {ng,ng+4,ng+8,ng+12}
    // gets distinct sub-slots -> 16 lanes cover all 32 banks.
    const int fo0 = ng * 8 + (( g     ) & 3) * 2;
    const int fo1 = ng * 8 + ((1 + g  ) & 3) * 2;
    const int fo2 = ng * 8 + ((2 + g  ) & 3) * 2;
    const int fo3 = ng * 8 + ((3 + g  ) & 3) * 2;

    ull S[4][4];
#pragma unroll
    for (int p = 0; p < 4; p++)
#pragma unroll
        for (int j = 0; j < 4; j++) S[p][j] = 0ULL;

    const float Dh = Dv[h];
    const float* xcb = g_xconv + (size_t)bi * SEQLEN * CONV_DIM;
    const float* dAb = g_dA  + (size_t)bi * SEQLEN * NHEADS + h;
    const float* dtb = g_dtp + (size_t)bi * SEQLEN * NHEADS + h;
    const int xofs = h * 64 + ph * 32;

    auto stage4 = [&](int t, int pi) {
#pragma unroll
        for (int k = 0; k < 3; k++) {
            int c = tid + k * 128;
            if (c >= 296) break;
            int s = c / 74;
            int cc = c - s * 74;
            const float* rowp = xcb + (size_t)(t + s) * CONV_DIM;
            if (cc < 32)       cp_async16(smem_u32(&sB[pi][s][cc * 4]),  rowp + D_INNER + cc * 4, 16);
            else if (cc < 64)  cp_async16(smem_u32(&sC[pi][s][(cc - 32) * 4]), rowp + D_INNER + D_STATE + (cc - 32) * 4, 16);
            else if (cc < 72)  cp_async16(smem_u32(&sxs[pi][s][(cc - 64) * 4]), rowp + xofs + (cc - 64) * 4, 16);
            else if (cc == 72) cp_async4(smem_u32(&ssc[pi][s][0]), dAb + (size_t)(t + s) * NHEADS);
            else               cp_async4(smem_u32(&ssc[pi][s][1]), dtb + (size_t)(t + s) * NHEADS);
        }
    };

    stage4(0, 0);  cp_commit();
    stage4(4, 1);  cp_commit();
    stage4(8, 2);  cp_commit();
    stage4(12, 3); cp_commit();

    float* yout = g_y + (size_t)bi * SEQLEN * D_INNER + xofs + pg * 4;

    const int NITER = SEQLEN / 4;
    for (int it = 0; it < NITER; it++) {
        const int t = it * 4;
        const int pi = it & 3;
        cp_wait<3>();
        __syncthreads();

        // hoist scalars for all 4 steps (latencies overlap)
        float2 sc[4];
        float4 xs[4];
#pragma unroll
        for (int s = 0; s < 4; s++) {
            sc[s] = *(const float2*)&ssc[pi][s][0];
            xs[s] = *(const float4*)&sxs[pi][s][pg * 4];
        }

        ull Bb[2][4], Cb[2][4];
        {
            const float* bp = &sB[pi][0][0];
            const float* cp2 = &sC[pi][0][0];
            Bb[0][0] = *(const ull*)(bp + fo0); Bb[0][1] = *(const ull*)(bp + fo1);
            Bb[0][2] = *(const ull*)(bp + fo2); Bb[0][3] = *(const ull*)(bp + fo3);
            Cb[0][0] = *(const ull*)(cp2 + fo0); Cb[0][1] = *(const ull*)(cp2 + fo1);
            Cb[0][2] = *(const ull*)(cp2 + fo2); Cb[0][3] = *(const ull*)(cp2 + fo3);
        }

        float yv[4][4];   // [p][s]
#pragma unroll
        for (int s = 0; s < 4; s++) {
            const int cur = s & 1;
            if (s < 3) {
                const int nxt = cur ^ 1;
                const float* bp = &sB[pi][s + 1][0];
                const float* cp2 = &sC[pi][s + 1][0];
                Bb[nxt][0] = *(const ull*)(bp + fo0); Bb[nxt][1] = *(const ull*)(bp + fo1);
                Bb[nxt][2] = *(const ull*)(bp + fo2); Bb[nxt][3] = *(const ull*)(bp + fo3);
                Cb[nxt][0] = *(const ull*)(cp2 + fo0); Cb[nxt][1] = *(const ull*)(cp2 + fo1);
                Cb[nxt][2] = *(const ull*)(cp2 + fo2); Cb[nxt][3] = *(const ull*)(cp2 + fo3);
            }
            const ull dA2 = f2pack(sc[s].x);
            const float dtv = sc[s].y;
            const ull B0 = Bb[cur][0], B1 = Bb[cur][1], B2 = Bb[cur][2], B3 = Bb[cur][3];
            const ull C0 = Cb[cur][0], C1 = Cb[cur][1], C2 = Cb[cur][2], C3 = Cb[cur][3];
#pragma unroll
            for (int p = 0; p < 4; p++) {
                const float xv = ((const float*)&xs[s])[p];
                const ull xdt2 = f2pack(xv * dtv);
                ull a0, a1;
                S[p][0] = f2fma(dA2, S[p][0], f2mul(xdt2, B0)); a0 = f2mul(S[p][0], C0);
                S[p][1] = f2fma(dA2, S[p][1], f2mul(xdt2, B1)); a1 = f2mul(S[p][1], C1);
                S[p][2] = f2fma(dA2, S[p][2], f2mul(xdt2, B2)); a0 = f2fma(S[p][2], C2, a0);
                S[p][3] = f2fma(dA2, S[p][3], f2mul(xdt2, B3)); a1 = f2fma(S[p][3], C3, a1);
                yv[p][s] = f2sum(a0) + f2sum(a1);
            }
        }

        // batched butterfly reduction over 16 n-lanes
#pragma unroll
        for (int o = 1; o < 16; o <<= 1) {
#pragma unroll
            for (int p = 0; p < 4; p++)
#pragma unroll
                for (int s = 0; s < 4; s++)
                    yv[p][s] += __shfl_xor_sync(0xffffffffu, yv[p][s], o);
        }
        if (ng == 0) {
#pragma unroll
            for (int s = 0; s < 4; s++) {
                float4 v;
                v.x = fmaf(Dh, ((const float*)&xs[s])[0], yv[0][s]);
                v.y = fmaf(Dh, ((const float*)&xs[s])[1], yv[1][s]);
                v.z = fmaf(Dh, ((const float*)&xs[s])[2], yv[2][s]);
                v.w = fmaf(Dh, ((const float*)&xs[s])[3], yv[3][s]);
                *(float4*)(yout + (size_t)(t + s) * D_INNER) = v;
            }
        }
        __syncthreads();
        if (t + 16 < SEQLEN) stage4(t + 16, pi);
        cp_commit();
    }
}

// =====================================================================
__global__ __launch_bounds__(256) void gatenorm_kernel(const float* __restrict__ nw)
{
    int row = blockIdx.x;
    int tid = threadIdx.x;
    const float* yr = g_y + (size_t)row * D_INNER;
    const float* zr = g_zx + (size_t)row * D_IN_PROJ;
    float v[8];
    float ss = 0.f;
#pragma unroll
    for (int i = 0; i < 8; i++) {
        int c = tid + i * 256;
        float z = zr[c];
        float val = yr[c] * (z / (1.f + expf(-z)));
        v[i] = val;
        ss = fmaf(val, val, ss);
    }
#pragma unroll
    for (int o = 16; o; o >>= 1) ss += __shfl_xor_sync(0xffffffffu, ss, o);
    __shared__ float red[8];
    if ((tid & 31) == 0) red[tid >> 5] = ss;
    __syncthreads();
    float tot = red[0] + red[1] + red[2] + red[3] + red[4] + red[5] + red[6] + red[7];
    float scale = rsqrtf(tot * (1.0f / 2048.0f) + 1e-5f);
#pragma unroll
    for (int i = 0; i < 8; i++) {
        int c = tid + i * 256;
        float val = v[i] * scale * nw[c];
        __nv_bfloat16 h = __float2bfloat16_rn(val);
        g_nh[(size_t)row * D_INNER + c] = h;
        g_nl[(size_t)row * D_INNER + c] = __float2bfloat16_rn(val - __bfloat162float(h));
    }
}

// =====================================================================
extern "C" void kernel_launch(void* const* d_in, const int* in_sizes, int n_in,
                              void* d_out, int out_size)
{
    const float* x          = (const float*)d_in[0];
    const float* in_proj_w  = (const float*)d_in[1];
    const float* conv_w     = (const float*)d_in[2];
    const float* conv_b     = (const float*)d_in[3];
    const float* dt_bias    = (const float*)d_in[4];
    const float* A_log      = (const float*)d_in[5];
    const float* Dv         = (const float*)d_in[6];
    const float* norm_w     = (const float*)d_in[7];
    const float* out_proj_w = (const float*)d_in[8];
    float* out = (float*)d_out;

    float *zx;
    __nv_bfloat16 *xh, *xl, *w1h, *w1l, *w2h, *w2l, *nh, *nl;
    cudaGetSymbolAddress((void**)&zx, g_zx);
    cudaGetSymbolAddress((void**)&xh, g_xhb);
    cudaGetSymbolAddress((void**)&xl, g_xlb);
    cudaGetSymbolAddress((void**)&w1h, g_w1h);
    cudaGetSymbolAddress((void**)&w1l, g_w1l);
    cudaGetSymbolAddress((void**)&w2h, g_w2h);
    cudaGetSymbolAddress((void**)&w2l, g_w2l);
    cudaGetSymbolAddress((void**)&nh, g_nh);
    cudaGetSymbolAddress((void**)&nl, g_nl);

    cudaFuncSetAttribute(gemm_mma, cudaFuncAttributeMaxDynamicSharedMemorySize, GSMEM);

    split_kernel<<<(BL * D_MODEL + 255) / 256, 256>>>(x, xh, xl, BL * D_MODEL);
    split_kernel<<<(D_IN_PROJ * D_MODEL + 255) / 256, 256>>>(in_proj_w, w1h, w1l, D_IN_PROJ * D_MODEL);
    split_kernel<<<(D_MODEL * D_INNER + 255) / 256, 256>>>(out_proj_w, w2h, w2l, D_MODEL * D_INNER);

    gemm_mma<<<dim3((D_IN_PROJ + 127) / 128, BL / 128), 256, GSMEM>>>(
        xh, xl, w1h, w1l, zx, nullptr, BL, D_IN_PROJ, D_MODEL);

    conv_silu_kernel<<<dim3(CONV_DIM / 256, BL), 256>>>(conv_w, conv_b);
    dt_kernel<<<(BL * NHEADS) / 256, 256>>>(dt_bias, A_log);

    scan_kernel<<<BATCH * NHEADS * 2, 128>>>(Dv);

    gatenorm_kernel<<<BL, 256>>>(norm_w);

    gemm_mma<<<dim3(D_MODEL / 128, BL / 128), 256, GSMEM>>>(
        nh, nl, w2h, w2l, out, x, BL, D_MODEL, D_INNER);
}